// round 16
// baseline (speedup 1.0000x reference)
#include <cuda_runtime.h>
#include <cstdint>
#include <math.h>
#include <math_constants.h>

#define Bq 16
#define Nq 256
#define Dq 256
#define Hq 8
#define HDq 32
#define PDq 4
#define RATIOq 4
#define ROWS (Bq*Nq)          // 4096
#define DFF (RATIOq*Dq)       // 1024

typedef unsigned long long u64;

__device__ float g_bias[(size_t)Bq*Hq*Nq*Nq];   // [B,H,N,N]
__device__ float g_xn[(size_t)ROWS*Dq];
__device__ float g_qkv[(size_t)ROWS*3*Dq];      // [B,N,3,H,HD]
__device__ float g_attout[(size_t)ROWS*Dq];
__device__ float g_x2[(size_t)ROWS*Dq];
__device__ float g_hid[(size_t)ROWS*DFF];
__device__ float g_wt[786432];                  // tf32-rounded weights

__device__ __forceinline__ float gelu_f(float x) {
    return 0.5f * x * (1.0f + erff(x * 0.70710678118654752f));
}

// tanh-approx GELU (HW tanh.approx.f32) — pairwise bias path only
__device__ __forceinline__ float gelu_t(float x) {
    float t = fmaf(0.044715f * x, x * x, x);
    float u = 0.79788456080286536f * t;
    float th;
    asm("tanh.approx.f32 %0, %1;" : "=f"(th) : "f"(u));
    return 0.5f * x * (1.0f + th);
}

__device__ __forceinline__ float tf32r(float x) {
    uint32_t o;
    asm("cvt.rna.tf32.f32 %0, %1;" : "=r"(o) : "f"(x));
    return __uint_as_float(o);
}

// ---- packed f32x2 helpers ----
__device__ __forceinline__ u64 pk2(float lo, float hi) {
    u64 r; asm("mov.b64 %0, {%1, %2};" : "=l"(r) : "f"(lo), "f"(hi)); return r;
}
__device__ __forceinline__ void upk2(float& lo, float& hi, u64 v) {
    asm("mov.b64 {%0, %1}, %2;" : "=f"(lo), "=f"(hi) : "l"(v));
}
__device__ __forceinline__ u64 fma2(u64 a, u64 b, u64 c) {
    u64 d; asm("fma.rn.f32x2 %0, %1, %2, %3;" : "=l"(d) : "l"(a), "l"(b), "l"(c)); return d;
}

// ---- cp.async helpers ----
__device__ __forceinline__ void cpa16(uint32_t s, const float* g) {
    asm volatile("cp.async.cg.shared.global [%0], [%1], 16;" :: "r"(s), "l"(g));
}
__device__ __forceinline__ void cpa_commit() {
    asm volatile("cp.async.commit_group;" ::: "memory");
}
template<int N> __device__ __forceinline__ void cpa_wait() {
    asm volatile("cp.async.wait_group %0;" :: "n"(N) : "memory");
}

__device__ __forceinline__ void mma_tf32(float c[4],
    uint32_t a0, uint32_t a1, uint32_t a2, uint32_t a3,
    uint32_t b0, uint32_t b1)
{
    asm("mma.sync.aligned.m16n8k8.row.col.f32.tf32.tf32.f32 "
        "{%0,%1,%2,%3}, {%4,%5,%6,%7}, {%8,%9}, {%0,%1,%2,%3};\n"
        : "+f"(c[0]), "+f"(c[1]), "+f"(c[2]), "+f"(c[3])
        : "r"(a0), "r"(a1), "r"(a2), "r"(a3), "r"(b0), "r"(b1));
}

// ---------------- Kernel 0: weight tf32 conversion ---------------------------
__global__ void cvtw_kernel(const float* __restrict__ qkv_w, const float* __restrict__ proj_w,
                            const float* __restrict__ mlp_w1, const float* __restrict__ mlp_w2)
{
    int i = blockIdx.x * 256 + threadIdx.x;
    float v;
    if      (i < 196608) v = qkv_w[i];
    else if (i < 262144) v = proj_w[i - 196608];
    else if (i < 524288) v = mlp_w1[i - 262144];
    else                 v = mlp_w2[i - 524288];
    g_wt[i] = tf32r(v);
}

// ---------------- Kernel 1: pairwise bias MLP (kt-outer mma loop) ------------
#define W2_STR 72
#define H1_STR 68
__global__ void __launch_bounds__(256, 2) pairwise_kernel(
    const float* __restrict__ u,
    const float* __restrict__ w1, const float* __restrict__ b1,
    const float* __restrict__ w2, const float* __restrict__ b2,
    const float* __restrict__ w3, const float* __restrict__ b3)
{
    extern __shared__ float sm[];
    float* w2s = sm;                    // 64*72
    float* h1s = sm + 64*W2_STR;        // 256*68

    __shared__ __align__(16) float w1s[4*64];
    __shared__ __align__(16) float b1s[64];
    __shared__ __align__(16) float b2s[64];
    __shared__ __align__(16) float w3s[64*8];
    __shared__ __align__(16) float b3s[8];

    int tid = threadIdx.x;
    int lane = tid & 31, w = tid >> 5;
    int tg = lane >> 2;
    int tr = lane & 3;

    w1s[tid] = w1[tid];
    if (tid < 64) { b1s[tid] = b1[tid]; b2s[tid] = b2[tid]; }
    w3s[tid] = w3[tid]; w3s[tid + 256] = w3[tid + 256];
    if (tid < 8) b3s[tid] = b3[tid];
    #pragma unroll
    for (int i = tid; i < 4096; i += 256) {
        int k = i >> 6, n = i & 63;
        w2s[k*W2_STR + n] = tf32r(w2[i]);
    }
    __syncthreads();

    // ---- layer 1 (f32x2 + tanh-GELU)
    int pos0 = blockIdx.x * 256;
    float4 uv = reinterpret_cast<const float4*>(u)[pos0 + tid];
    u64 ux = pk2(uv.x, uv.x), uy = pk2(uv.y, uv.y);
    u64 uz = pk2(uv.z, uv.z), uw = pk2(uv.w, uv.w);
    #pragma unroll
    for (int k4 = 0; k4 < 16; k4++) {
        float4 hv;
        float* hp = &hv.x;
        #pragma unroll
        for (int p = 0; p < 2; p++) {
            int k = k4*4 + p*2;
            u64 acc = *reinterpret_cast<const u64*>(&b1s[k]);
            acc = fma2(ux, *reinterpret_cast<const u64*>(&w1s[k      ]), acc);
            acc = fma2(uy, *reinterpret_cast<const u64*>(&w1s[64  + k]), acc);
            acc = fma2(uz, *reinterpret_cast<const u64*>(&w1s[128 + k]), acc);
            acc = fma2(uw, *reinterpret_cast<const u64*>(&w1s[192 + k]), acc);
            float lo, hi; upk2(lo, hi, acc);
            hp[p*2 + 0] = tf32r(gelu_t(lo));
            hp[p*2 + 1] = tf32r(gelu_t(hi));
        }
        *reinterpret_cast<float4*>(&h1s[tid*H1_STR + k4*4]) = hv;
    }
    __syncwarp();

    // ---- layer 2 mma, kt-outer (A loaded once per kt), nt in 2 halves
    int rbase = w * 32;
    u64 outP[4][4];
    #pragma unroll
    for (int r = 0; r < 4; r++)
        #pragma unroll
        for (int j = 0; j < 4; j++) outP[r][j] = 0ull;

    #pragma unroll
    for (int half = 0; half < 2; half++) {
        float c[2][4][4];
        #pragma unroll
        for (int mt = 0; mt < 2; mt++)
            #pragma unroll
            for (int ntl = 0; ntl < 4; ntl++)
                #pragma unroll
                for (int q = 0; q < 4; q++) c[mt][ntl][q] = 0.f;

        #pragma unroll
        for (int kt = 0; kt < 8; kt++) {
            uint32_t a[2][4];
            #pragma unroll
            for (int mt = 0; mt < 2; mt++) {
                int r = rbase + mt*16 + tg;
                a[mt][0] = __float_as_uint(h1s[ r     *H1_STR + kt*8 + tr    ]);
                a[mt][1] = __float_as_uint(h1s[(r + 8)*H1_STR + kt*8 + tr    ]);
                a[mt][2] = __float_as_uint(h1s[ r     *H1_STR + kt*8 + tr + 4]);
                a[mt][3] = __float_as_uint(h1s[(r + 8)*H1_STR + kt*8 + tr + 4]);
            }
            #pragma unroll
            for (int ntl = 0; ntl < 4; ntl++) {
                int nt = half*4 + ntl;
                uint32_t bf0 = __float_as_uint(w2s[(kt*8 + tr    )*W2_STR + nt*8 + tg]);
                uint32_t bf1 = __float_as_uint(w2s[(kt*8 + tr + 4)*W2_STR + nt*8 + tg]);
                mma_tf32(c[0][ntl], a[0][0], a[0][1], a[0][2], a[0][3], bf0, bf1);
                mma_tf32(c[1][ntl], a[1][0], a[1][1], a[1][2], a[1][3], bf0, bf1);
            }
        }

        // layer-3 partials for this half (f32x2)
        #pragma unroll
        for (int ntl = 0; ntl < 4; ntl++) {
            int nt = half*4 + ntl;
            #pragma unroll
            for (int cc = 0; cc < 2; cc++) {
                int n = nt*8 + 2*tr + cc;
                float b2n = b2s[n];
                u64 w3p0 = *reinterpret_cast<const u64*>(&w3s[n*8    ]);
                u64 w3p1 = *reinterpret_cast<const u64*>(&w3s[n*8 + 2]);
                u64 w3p2 = *reinterpret_cast<const u64*>(&w3s[n*8 + 4]);
                u64 w3p3 = *reinterpret_cast<const u64*>(&w3s[n*8 + 6]);
                #pragma unroll
                for (int mt = 0; mt < 2; mt++) {
                    float glo = gelu_t(c[mt][ntl][cc]     + b2n);
                    float ghi = gelu_t(c[mt][ntl][cc + 2] + b2n);
                    u64 g2lo = pk2(glo, glo);
                    u64 g2hi = pk2(ghi, ghi);
                    u64* olo = outP[mt*2 + 0];
                    u64* ohi = outP[mt*2 + 1];
                    olo[0] = fma2(g2lo, w3p0, olo[0]); olo[1] = fma2(g2lo, w3p1, olo[1]);
                    olo[2] = fma2(g2lo, w3p2, olo[2]); olo[3] = fma2(g2lo, w3p3, olo[3]);
                    ohi[0] = fma2(g2hi, w3p0, ohi[0]); ohi[1] = fma2(g2hi, w3p1, ohi[1]);
                    ohi[2] = fma2(g2hi, w3p2, ohi[2]); ohi[3] = fma2(g2hi, w3p3, ohi[3]);
                }
            }
        }
    }

    // ---- reduce across 4 threads sharing each row; write bias
    #pragma unroll
    for (int rr = 0; rr < 4; rr++) {
        int mt = rr >> 1, hi = rr & 1;
        int lpos = rbase + mt*16 + tg + hi*8;
        int pos = pos0 + lpos;
        float outA[8];
        #pragma unroll
        for (int j = 0; j < 4; j++) upk2(outA[2*j], outA[2*j+1], outP[rr][j]);
        #pragma unroll
        for (int h = 0; h < 8; h++) {
            float v = outA[h];
            v += __shfl_xor_sync(0xffffffffu, v, 1);
            v += __shfl_xor_sync(0xffffffffu, v, 2);
            outA[h] = v;
        }
        int b  = pos >> 16;
        int ij = pos & 65535;
        size_t base = ((size_t)b * 8) * 65536 + (size_t)ij;
        int h0 = 2*tr;
        g_bias[base + (size_t)(h0    )*65536] = gelu_t(outA[h0    ] + b3s[h0    ]);
        g_bias[base + (size_t)(h0 + 1)*65536] = gelu_t(outA[h0 + 1] + b3s[h0 + 1]);
    }
}

// ---------------- Kernel 2: LayerNorm (tf32-rounded output) ------------------
__global__ void ln_kernel(const float* __restrict__ x,
                          const float* __restrict__ gg, const float* __restrict__ bb,
                          float* __restrict__ y)
{
    int w = threadIdx.x >> 5, lane = threadIdx.x & 31;
    int row = blockIdx.x * 8 + w;
    const float4* xr = reinterpret_cast<const float4*>(x + (size_t)row * 256);
    float4 a = xr[lane*2], c = xr[lane*2 + 1];
    float s = a.x + a.y + a.z + a.w + c.x + c.y + c.z + c.w;
    #pragma unroll
    for (int o = 16; o; o >>= 1) s += __shfl_xor_sync(0xffffffffu, s, o);
    float mu = s * (1.0f / 256.0f);
    float dx[8] = {a.x-mu, a.y-mu, a.z-mu, a.w-mu, c.x-mu, c.y-mu, c.z-mu, c.w-mu};
    float ss = 0.f;
    #pragma unroll
    for (int q = 0; q < 8; q++) ss += dx[q]*dx[q];
    #pragma unroll
    for (int o = 16; o; o >>= 1) ss += __shfl_xor_sync(0xffffffffu, ss, o);
    float rstd = rsqrtf(ss * (1.0f/256.0f) + 1e-5f);
    const float4* gr = reinterpret_cast<const float4*>(gg);
    const float4* br = reinterpret_cast<const float4*>(bb);
    float4 g0 = gr[lane*2], g1 = gr[lane*2+1];
    float4 b0 = br[lane*2], b1 = br[lane*2+1];
    float4 o0, o1;
    o0.x = tf32r(fmaf(dx[0]*rstd, g0.x, b0.x)); o0.y = tf32r(fmaf(dx[1]*rstd, g0.y, b0.y));
    o0.z = tf32r(fmaf(dx[2]*rstd, g0.z, b0.z)); o0.w = tf32r(fmaf(dx[3]*rstd, g0.w, b0.w));
    o1.x = tf32r(fmaf(dx[4]*rstd, g1.x, b1.x)); o1.y = tf32r(fmaf(dx[5]*rstd, g1.y, b1.y));
    o1.z = tf32r(fmaf(dx[6]*rstd, g1.z, b1.z)); o1.w = tf32r(fmaf(dx[7]*rstd, g1.w, b1.w));
    float4* yr = reinterpret_cast<float4*>(y + (size_t)row * 256);
    yr[lane*2] = o0; yr[lane*2 + 1] = o1;
}

// ---------------- Kernel 3: tf32 TC GEMM, cp.async double-buffered -----------
#define SA 4608              // 128*36 floats
#define SB 2304              // 32*72 floats
#define STG (SA + SB)        // per-stage floats
#define GEMM_SMEM (2*STG*4)  // 55296 bytes
template<int ACT, bool RES, bool CVT>
__global__ void __launch_bounds__(256) gemm_tc(
    const float* __restrict__ A, const float* __restrict__ W,
    const float* __restrict__ bias, const float* __restrict__ res,
    float* __restrict__ C, int K, int Nc)
{
    extern __shared__ float smx[];
    int tid = threadIdx.x;
    int lane = tid & 31, warp = tid >> 5;
    int tg = lane >> 2, tr = lane & 3;
    int wm = warp & 3, wn = warp >> 2;
    int row0 = blockIdx.y * 128, col0 = blockIdx.x * 64;

    float c[2][4][4];
    #pragma unroll
    for (int mt = 0; mt < 2; mt++)
        #pragma unroll
        for (int nt = 0; nt < 4; nt++)
            #pragma unroll
            for (int q = 0; q < 4; q++) c[mt][nt][q] = 0.f;

    int ar = tid >> 1, ah = (tid & 1) * 16;
    int br = tid >> 3, bc = (tid & 7) * 8;
    const float* Ap = A + (size_t)(row0 + ar) * K + ah;
    const float* Wp = W + (size_t)br * Nc + col0 + bc;
    uint32_t sbase = (uint32_t)__cvta_generic_to_shared(smx);

    auto issue = [&](int k0, int stg) {
        uint32_t sa = sbase + (stg*STG + ar*36 + ah) * 4u;
        #pragma unroll
        for (int q = 0; q < 4; q++) cpa16(sa + q*16, Ap + k0 + q*4);
        uint32_t sb = sbase + (stg*STG + SA + br*72 + bc) * 4u;
        cpa16(sb,      Wp + (size_t)k0 * Nc);
        cpa16(sb + 16, Wp + (size_t)k0 * Nc + 4);
        cpa_commit();
    };

    issue(0, 0);
    int cur = 0;
    for (int k0 = 0; k0 < K; k0 += 32) {
        bool hasNext = (k0 + 32) < K;
        if (hasNext) { issue(k0 + 32, cur ^ 1); cpa_wait<1>(); }
        else         { cpa_wait<0>(); }
        __syncthreads();

        const float* As = smx + cur*STG;
        const float* Bs = As + SA;
        #pragma unroll
        for (int kk = 0; kk < 4; kk++) {
            uint32_t bf0[4], bf1[4];
            #pragma unroll
            for (int nt = 0; nt < 4; nt++) {
                bf0[nt] = __float_as_uint(Bs[(kk*8 + tr    )*72 + wn*32 + nt*8 + tg]);
                bf1[nt] = __float_as_uint(Bs[(kk*8 + tr + 4)*72 + wn*32 + nt*8 + tg]);
            }
            #pragma unroll
            for (int mt = 0; mt < 2; mt++) {
                int rr = wm*32 + mt*16 + tg;
                uint32_t fa0 = __float_as_uint(As[ rr     *36 + kk*8 + tr    ]);
                uint32_t fa1 = __float_as_uint(As[(rr + 8)*36 + kk*8 + tr    ]);
                uint32_t fa2 = __float_as_uint(As[ rr     *36 + kk*8 + tr + 4]);
                uint32_t fa3 = __float_as_uint(As[(rr + 8)*36 + kk*8 + tr + 4]);
                #pragma unroll
                for (int nt = 0; nt < 4; nt++)
                    mma_tf32(c[mt][nt], fa0, fa1, fa2, fa3, bf0[nt], bf1[nt]);
            }
        }
        __syncthreads();
        cur ^= 1;
    }

    #pragma unroll
    for (int mt = 0; mt < 2; mt++) {
        int r_lo = row0 + wm*32 + mt*16 + tg;
        #pragma unroll
        for (int nt = 0; nt < 4; nt++) {
            int cc0 = col0 + wn*32 + nt*8 + 2*tr;
            float bx = bias[cc0], by = bias[cc0 + 1];
            float v00 = c[mt][nt][0] + bx, v01 = c[mt][nt][1] + by;
            float v10 = c[mt][nt][2] + bx, v11 = c[mt][nt][3] + by;
            if (ACT == 1) { v00 = gelu_f(v00); v01 = gelu_f(v01); v10 = gelu_f(v10); v11 = gelu_f(v11); }
            if (RES) {
                v00 += res[(size_t)r_lo * Nc + cc0];     v01 += res[(size_t)r_lo * Nc + cc0 + 1];
                v10 += res[(size_t)(r_lo+8) * Nc + cc0]; v11 += res[(size_t)(r_lo+8) * Nc + cc0 + 1];
            }
            if (CVT) { v00 = tf32r(v00); v01 = tf32r(v01); v10 = tf32r(v10); v11 = tf32r(v11); }
            *reinterpret_cast<float2*>(&C[(size_t)r_lo * Nc + cc0])     = make_float2(v00, v01);
            *reinterpret_cast<float2*>(&C[(size_t)(r_lo+8) * Nc + cc0]) = make_float2(v10, v11);
        }
    }
}

// ---------------- Kernel 4: fused attention (transposed V tile) --------------
#define VT_STR 260
__global__ void attn_kernel(const unsigned char* __restrict__ mask)
{
    extern __shared__ float sm[];
    float* kT = sm;                   // [32][256]
    float* vT = sm + 32*256;          // [32][260]
    float* pS = vT + 32*VT_STR;       // [16][256]

    int bh = blockIdx.x;
    int b = bh >> 3, h = bh & 7;
    int tid = threadIdx.x;
    int w = tid >> 5, lane = tid & 31;

    const float* kp = g_qkv + ((size_t)(b*256 + tid)) * 768 + 256 + h*32;
    const float* vp = kp + 256;
    #pragma unroll
    for (int q = 0; q < 8; q++) {
        float4 kv = *reinterpret_cast<const float4*>(kp + q*4);
        kT[(q*4+0)*256 + tid] = kv.x;
        kT[(q*4+1)*256 + tid] = kv.y;
        kT[(q*4+2)*256 + tid] = kv.z;
        kT[(q*4+3)*256 + tid] = kv.w;
        float4 vv = *reinterpret_cast<const float4*>(vp + q*4);
        vT[(q*4+0)*VT_STR + tid] = vv.x;
        vT[(q*4+1)*VT_STR + tid] = vv.y;
        vT[(q*4+2)*VT_STR + tid] = vv.z;
        vT[(q*4+3)*VT_STR + tid] = vv.w;
    }
    __syncthreads();

    const float isq = 0.17677669529663689f;
    const unsigned char* mp = mask + b*256;
    uchar4 m0 = *reinterpret_cast<const uchar4*>(mp + lane*4);
    uchar4 m1 = *reinterpret_cast<const uchar4*>(mp + 128 + lane*4);

    int t0 = blockIdx.y * 64;
    for (int t = 0; t < 4; t++) {
        int r0 = t0 + t*16 + w*2;
        const float* qp0 = g_qkv + ((size_t)(b*256 + r0)) * 768 + h*32;
        const float* qp1 = qp0 + 768;
        float qr0[32], qr1[32];
        #pragma unroll
        for (int q = 0; q < 8; q++) {
            float4 f0 = *reinterpret_cast<const float4*>(qp0 + q*4);
            qr0[q*4+0] = f0.x; qr0[q*4+1] = f0.y; qr0[q*4+2] = f0.z; qr0[q*4+3] = f0.w;
            float4 f1 = *reinterpret_cast<const float4*>(qp1 + q*4);
            qr1[q*4+0] = f1.x; qr1[q*4+1] = f1.y; qr1[q*4+2] = f1.z; qr1[q*4+3] = f1.w;
        }
        u64 A0[4] = {0,0,0,0}, A1[4] = {0,0,0,0};
        #pragma unroll
        for (int hd = 0; hd < 32; hd++) {
            float4 k0 = *reinterpret_cast<const float4*>(&kT[hd*256 + lane*4]);
            float4 k1 = *reinterpret_cast<const float4*>(&kT[hd*256 + 128 + lane*4]);
            const u64* k0p = reinterpret_cast<const u64*>(&k0);
            const u64* k1p = reinterpret_cast<const u64*>(&k1);
            u64 q0p = pk2(qr0[hd], qr0[hd]);
            u64 q1p = pk2(qr1[hd], qr1[hd]);
            A0[0] = fma2(q0p, k0p[0], A0[0]); A0[1] = fma2(q0p, k0p[1], A0[1]);
            A0[2] = fma2(q0p, k1p[0], A0[2]); A0[3] = fma2(q0p, k1p[1], A0[3]);
            A1[0] = fma2(q1p, k0p[0], A1[0]); A1[1] = fma2(q1p, k0p[1], A1[1]);
            A1[2] = fma2(q1p, k1p[0], A1[2]); A1[3] = fma2(q1p, k1p[1], A1[3]);
        }
        float a0[8], a1[8];
        #pragma unroll
        for (int j = 0; j < 4; j++) {
            upk2(a0[2*j], a0[2*j+1], A0[j]);
            upk2(a1[2*j], a1[2*j+1], A1[j]);
        }

        #pragma unroll
        for (int rr = 0; rr < 2; rr++) {
            float* acc = rr ? a1 : a0;
            int i = r0 + rr;
            const float* bp = g_bias + ((size_t)bh * 256 + i) * 256;
            float4 bb0 = *reinterpret_cast<const float4*>(bp + lane*4);
            float4 bb1 = *reinterpret_cast<const float4*>(bp + 128 + lane*4);
            float l[8];
            l[0] = fmaf(acc[0], isq, bb0.x); l[1] = fmaf(acc[1], isq, bb0.y);
            l[2] = fmaf(acc[2], isq, bb0.z); l[3] = fmaf(acc[3], isq, bb0.w);
            l[4] = fmaf(acc[4], isq, bb1.x); l[5] = fmaf(acc[5], isq, bb1.y);
            l[6] = fmaf(acc[6], isq, bb1.z); l[7] = fmaf(acc[7], isq, bb1.w);
            if (m0.x) l[0] = -CUDART_INF_F; if (m0.y) l[1] = -CUDART_INF_F;
            if (m0.z) l[2] = -CUDART_INF_F; if (m0.w) l[3] = -CUDART_INF_F;
            if (m1.x) l[4] = -CUDART_INF_F; if (m1.y) l[5] = -CUDART_INF_F;
            if (m1.z) l[6] = -CUDART_INF_F; if (m1.w) l[7] = -CUDART_INF_F;

            float mx = l[0];
            #pragma unroll
            for (int c = 1; c < 8; c++) mx = fmaxf(mx, l[c]);
            #pragma unroll
            for (int o = 16; o; o >>= 1) mx = fmaxf(mx, __shfl_xor_sync(0xffffffffu, mx, o));
            float e[8], s = 0.f;
            #pragma unroll
            for (int c = 0; c < 8; c++) { e[c] = expf(l[c] - mx); s += e[c]; }
            #pragma unroll
            for (int o = 16; o; o >>= 1) s += __shfl_xor_sync(0xffffffffu, s, o);
            float inv = 1.0f / s;
            int pr = w*2 + rr;
            *reinterpret_cast<float4*>(&pS[pr*256 + lane*4]) =
                make_float4(e[0]*inv, e[1]*inv, e[2]*inv, e[3]*inv);
            *reinterpret_cast<float4*>(&pS[pr*256 + 128 + lane*4]) =
                make_float4(e[4]*inv, e[5]*inv, e[6]*inv, e[7]*inv);
        }
        __syncwarp();

        // PV: lane = hd; vT row contiguous -> one LDS.128 per 4 j's
        u64 O0 = 0ull, O1 = 0ull;
        const float* vrow = &vT[lane*VT_STR];
        #pragma unroll 8
        for (int j4 = 0; j4 < 64; j4++) {
            float4 p0 = *reinterpret_cast<const float4*>(&pS[(w*2    )*256 + j4*4]);
            float4 p1 = *reinterpret_cast<const float4*>(&pS[(w*2 + 1)*256 + j4*4]);
            float4 vv = *reinterpret_cast<const float4*>(vrow + j4*4);
            const u64* p0p = reinterpret_cast<const u64*>(&p0);
            const u64* p1p = reinterpret_cast<const u64*>(&p1);
            const u64* vvp = reinterpret_cast<const u64*>(&vv);
            O0 = fma2(p0p[0], vvp[0], O0); O0 = fma2(p0p[1], vvp[1], O0);
            O1 = fma2(p1p[0], vvp[0], O1); O1 = fma2(p1p[1], vvp[1], O1);
        }
        float o0lo, o0hi, o1lo, o1hi;
        upk2(o0lo, o0hi, O0); upk2(o1lo, o1hi, O1);
        g_attout[((size_t)(b*256 + r0    )) * 256 + h*32 + lane] = tf32r(o0lo + o0hi);
        g_attout[((size_t)(b*256 + r0 + 1)) * 256 + h*32 + lane] = tf32r(o1lo + o1hi);
        __syncwarp();
    }
}

// ---------------- launch (forked streams: pairwise || ln1+qkv) ---------------
extern "C" void kernel_launch(void* const* d_in, const int* in_sizes, int n_in,
                              void* d_out, int out_size)
{
    const float* x      = (const float*)d_in[0];
    const float* u      = (const float*)d_in[1];
    const unsigned char* mask = (const unsigned char*)d_in[2];
    const float* n1_g   = (const float*)d_in[3];
    const float* n1_b   = (const float*)d_in[4];
    const float* qkv_w  = (const float*)d_in[5];
    const float* qkv_b  = (const float*)d_in[6];
    const float* proj_w = (const float*)d_in[7];
    const float* proj_b = (const float*)d_in[8];
    const float* n2_g   = (const float*)d_in[9];
    const float* n2_b   = (const float*)d_in[10];
    const float* mlp_w1 = (const float*)d_in[11];
    const float* mlp_b1 = (const float*)d_in[12];
    const float* mlp_w2 = (const float*)d_in[13];
    const float* mlp_b2 = (const float*)d_in[14];
    const float* pw_w1  = (const float*)d_in[15];
    const float* pw_b1  = (const float*)d_in[16];
    const float* pw_w2  = (const float*)d_in[17];
    const float* pw_b2  = (const float*)d_in[18];
    const float* pw_w3  = (const float*)d_in[19];
    const float* pw_b3  = (const float*)d_in[20];
    float* out = (float*)d_out;

    float* xn  = nullptr; float* qkv = nullptr; float* ao = nullptr;
    float* x2  = nullptr; float* hid = nullptr; float* wt = nullptr;
    cudaGetSymbolAddress((void**)&xn,  g_xn);
    cudaGetSymbolAddress((void**)&qkv, g_qkv);
    cudaGetSymbolAddress((void**)&ao,  g_attout);
    cudaGetSymbolAddress((void**)&x2,  g_x2);
    cudaGetSymbolAddress((void**)&hid, g_hid);
    cudaGetSymbolAddress((void**)&wt,  g_wt);

    cudaFuncSetAttribute(gemm_tc<0,false,false>, cudaFuncAttributeMaxDynamicSharedMemorySize, GEMM_SMEM);
    cudaFuncSetAttribute(gemm_tc<0,true,false>,  cudaFuncAttributeMaxDynamicSharedMemorySize, GEMM_SMEM);
    cudaFuncSetAttribute(gemm_tc<1,false,true>,  cudaFuncAttributeMaxDynamicSharedMemorySize, GEMM_SMEM);
    cudaFuncSetAttribute(gemm_tc<1,true,false>,  cudaFuncAttributeMaxDynamicSharedMemorySize, GEMM_SMEM);

    // fork/join resources (created fresh each call; kernel_launch runs only a
    // few times pre-replay, so not destroying them mid-capture is safe)
    cudaStream_t s2;
    cudaStreamCreateWithFlags(&s2, cudaStreamNonBlocking);
    cudaEvent_t eFork, eJoin;
    cudaEventCreateWithFlags(&eFork, cudaEventDisableTiming);
    cudaEventCreateWithFlags(&eJoin, cudaEventDisableTiming);

    // 0) weight tf32 conversion (needed by qkv branch)
    cvtw_kernel<<<786432/256, 256>>>(qkv_w, proj_w, mlp_w1, mlp_w2);

    // fork: branch stream does LN1 + qkv GEMM while main does pairwise
    cudaEventRecord(eFork, 0);
    cudaStreamWaitEvent(s2, eFork, 0);

    ln_kernel<<<ROWS/8, 256, 0, s2>>>(x, n1_g, n1_b, xn);
    gemm_tc<0,false,false><<<dim3(3*Dq/64, ROWS/128), 256, GEMM_SMEM, s2>>>(
        xn, wt, qkv_b, nullptr, qkv, Dq, 3*Dq);

    // 1) pairwise bias MLP (main stream)
    {
        int smem = (64*W2_STR + 256*H1_STR) * (int)sizeof(float);
        cudaFuncSetAttribute(pairwise_kernel, cudaFuncAttributeMaxDynamicSharedMemorySize, smem);
        pairwise_kernel<<<Bq*Nq*Nq/256, 256, smem>>>(u, pw_w1, pw_b1, pw_w2, pw_b2, pw_w3, pw_b3);
    }

    // join
    cudaEventRecord(eJoin, s2);
    cudaStreamWaitEvent(0, eJoin, 0);

    // 3) attention
    {
        int smem = (32*256 + 32*VT_STR + 16*256) * (int)sizeof(float);
        cudaFuncSetAttribute(attn_kernel, cudaFuncAttributeMaxDynamicSharedMemorySize, smem);
        dim3 grid(Bq*Hq, 4);
        attn_kernel<<<grid, 256, smem>>>(mask);
    }

    // 4) proj + residual
    gemm_tc<0,true,false><<<dim3(Dq/64, ROWS/128), 256, GEMM_SMEM>>>(
        ao, wt + 196608, proj_b, x, x2, Dq, Dq);

    // 5) LN2 + MLP
    ln_kernel<<<ROWS/8, 256>>>(x2, n2_g, n2_b, xn);
    gemm_tc<1,false,true><<<dim3(DFF/64, ROWS/128), 256, GEMM_SMEM>>>(
        xn, wt + 262144, mlp_b1, nullptr, hid, Dq, DFF);
    gemm_tc<1,true,false><<<dim3(Dq/64, ROWS/128), 256, GEMM_SMEM>>>(
        hid, wt + 524288, mlp_b2, x2, out, DFF, Dq);
}

// round 17
// speedup vs baseline: 1.0412x; 1.0412x over previous
#include <cuda_runtime.h>
#include <cstdint>
#include <math.h>
#include <math_constants.h>

#define Bq 16
#define Nq 256
#define Dq 256
#define Hq 8
#define HDq 32
#define PDq 4
#define RATIOq 4
#define ROWS (Bq*Nq)          // 4096
#define DFF (RATIOq*Dq)       // 1024

typedef unsigned long long u64;

__device__ float g_bias[(size_t)Bq*Hq*Nq*Nq];   // [B,H,N,N]
__device__ float g_xn[(size_t)ROWS*Dq];
__device__ float g_qkv[(size_t)ROWS*3*Dq];      // [B,N,3,H,HD]
__device__ float g_attout[(size_t)ROWS*Dq];
__device__ float g_x2[(size_t)ROWS*Dq];
__device__ float g_hid[(size_t)ROWS*DFF];
__device__ float g_wt[786432];                  // tf32-rounded weights

__device__ __forceinline__ float gelu_f(float x) {
    return 0.5f * x * (1.0f + erff(x * 0.70710678118654752f));
}

__device__ __forceinline__ float tf32r(float x) {
    uint32_t o;
    asm("cvt.rna.tf32.f32 %0, %1;" : "=r"(o) : "f"(x));
    return __uint_as_float(o);
}

// ---- packed f32x2 helpers ----
__device__ __forceinline__ u64 pk2(float lo, float hi) {
    u64 r; asm("mov.b64 %0, {%1, %2};" : "=l"(r) : "f"(lo), "f"(hi)); return r;
}
__device__ __forceinline__ void upk2(float& lo, float& hi, u64 v) {
    asm("mov.b64 {%0, %1}, %2;" : "=f"(lo), "=f"(hi) : "l"(v));
}
__device__ __forceinline__ u64 fma2(u64 a, u64 b, u64 c) {
    u64 d; asm("fma.rn.f32x2 %0, %1, %2, %3;" : "=l"(d) : "l"(a), "l"(b), "l"(c)); return d;
}
__device__ __forceinline__ u64 mul2(u64 a, u64 b) {
    u64 d; asm("mul.rn.f32x2 %0, %1, %2;" : "=l"(d) : "l"(a), "l"(b)); return d;
}
__device__ __forceinline__ u64 add2(u64 a, u64 b) {
    u64 d; asm("add.rn.f32x2 %0, %1, %2;" : "=l"(d) : "l"(a), "l"(b)); return d;
}

// packed-pair tanh-GELU: poly in f32x2, tanh via 2 scalar MUFU
__device__ __forceinline__ u64 gelu_t2(u64 x2, u64 CA, u64 CB, u64 CH) {
    u64 xsq = mul2(x2, x2);
    u64 cx  = mul2(x2, CA);
    u64 t   = fma2(cx, xsq, x2);     // x + 0.044715 x^3
    u64 uu  = mul2(t, CB);           // * sqrt(2/pi)
    float ul, uh; upk2(ul, uh, uu);
    float tl, th;
    asm("tanh.approx.f32 %0, %1;" : "=f"(tl) : "f"(ul));
    asm("tanh.approx.f32 %0, %1;" : "=f"(th) : "f"(uh));
    u64 th2 = pk2(tl, th);
    u64 hx  = mul2(x2, CH);          // 0.5x
    return fma2(hx, th2, hx);        // 0.5x + 0.5x*tanh
}

// ---- cp.async helpers ----
__device__ __forceinline__ void cpa16(uint32_t s, const float* g) {
    asm volatile("cp.async.cg.shared.global [%0], [%1], 16;" :: "r"(s), "l"(g));
}
__device__ __forceinline__ void cpa_commit() {
    asm volatile("cp.async.commit_group;" ::: "memory");
}
template<int N> __device__ __forceinline__ void cpa_wait() {
    asm volatile("cp.async.wait_group %0;" :: "n"(N) : "memory");
}

__device__ __forceinline__ void mma_tf32(float c[4],
    uint32_t a0, uint32_t a1, uint32_t a2, uint32_t a3,
    uint32_t b0, uint32_t b1)
{
    asm("mma.sync.aligned.m16n8k8.row.col.f32.tf32.tf32.f32 "
        "{%0,%1,%2,%3}, {%4,%5,%6,%7}, {%8,%9}, {%0,%1,%2,%3};\n"
        : "+f"(c[0]), "+f"(c[1]), "+f"(c[2]), "+f"(c[3])
        : "r"(a0), "r"(a1), "r"(a2), "r"(a3), "r"(b0), "r"(b1));
}

// ---------------- Kernel 0: weight tf32 conversion ---------------------------
__global__ void cvtw_kernel(const float* __restrict__ qkv_w, const float* __restrict__ proj_w,
                            const float* __restrict__ mlp_w1, const float* __restrict__ mlp_w2)
{
    int i = blockIdx.x * 256 + threadIdx.x;
    float v;
    if      (i < 196608) v = qkv_w[i];
    else if (i < 262144) v = proj_w[i - 196608];
    else if (i < 524288) v = mlp_w1[i - 262144];
    else                 v = mlp_w2[i - 524288];
    g_wt[i] = tf32r(v);
}

// ---------------- Kernel 1: pairwise bias MLP (packed GELU) ------------------
#define W2_STR 72
#define H1_STR 68
__global__ void __launch_bounds__(256, 2) pairwise_kernel(
    const float* __restrict__ u,
    const float* __restrict__ w1, const float* __restrict__ b1,
    const float* __restrict__ w2, const float* __restrict__ b2,
    const float* __restrict__ w3, const float* __restrict__ b3)
{
    extern __shared__ float sm[];
    float* w2s = sm;                    // 64*72
    float* h1s = sm + 64*W2_STR;        // 256*68

    __shared__ __align__(16) float w1s[4*64];
    __shared__ __align__(16) float b1s[64];
    __shared__ __align__(16) float b2s[64];
    __shared__ __align__(16) float w3s[64*8];
    __shared__ __align__(16) float b3s[8];

    int tid = threadIdx.x;
    int lane = tid & 31, w = tid >> 5;
    int tg = lane >> 2;
    int tr = lane & 3;

    w1s[tid] = w1[tid];
    if (tid < 64) { b1s[tid] = b1[tid]; b2s[tid] = b2[tid]; }
    w3s[tid] = w3[tid]; w3s[tid + 256] = w3[tid + 256];
    if (tid < 8) b3s[tid] = b3[tid];
    #pragma unroll
    for (int i = tid; i < 4096; i += 256) {
        int k = i >> 6, n = i & 63;
        w2s[k*W2_STR + n] = tf32r(w2[i]);
    }
    __syncthreads();

    const u64 CA = pk2(0.044715f, 0.044715f);
    const u64 CB = pk2(0.79788456080286536f, 0.79788456080286536f);
    const u64 CH = pk2(0.5f, 0.5f);

    // ---- layer 1 (f32x2 + packed tanh-GELU)
    int pos0 = blockIdx.x * 256;
    float4 uv = reinterpret_cast<const float4*>(u)[pos0 + tid];
    u64 ux = pk2(uv.x, uv.x), uy = pk2(uv.y, uv.y);
    u64 uz = pk2(uv.z, uv.z), uw = pk2(uv.w, uv.w);
    #pragma unroll
    for (int k4 = 0; k4 < 16; k4++) {
        float4 hv;
        float* hp = &hv.x;
        #pragma unroll
        for (int p = 0; p < 2; p++) {
            int k = k4*4 + p*2;
            u64 acc = *reinterpret_cast<const u64*>(&b1s[k]);
            acc = fma2(ux, *reinterpret_cast<const u64*>(&w1s[k      ]), acc);
            acc = fma2(uy, *reinterpret_cast<const u64*>(&w1s[64  + k]), acc);
            acc = fma2(uz, *reinterpret_cast<const u64*>(&w1s[128 + k]), acc);
            acc = fma2(uw, *reinterpret_cast<const u64*>(&w1s[192 + k]), acc);
            u64 ge = gelu_t2(acc, CA, CB, CH);
            float lo, hi; upk2(lo, hi, ge);
            hp[p*2 + 0] = tf32r(lo);
            hp[p*2 + 1] = tf32r(hi);
        }
        *reinterpret_cast<float4*>(&h1s[tid*H1_STR + k4*4]) = hv;
    }
    __syncwarp();

    // ---- layer 2 mma, kt-outer (A loaded once per kt), nt in 2 halves
    int rbase = w * 32;
    u64 outP[4][4];
    #pragma unroll
    for (int r = 0; r < 4; r++)
        #pragma unroll
        for (int j = 0; j < 4; j++) outP[r][j] = 0ull;

    #pragma unroll
    for (int half = 0; half < 2; half++) {
        float c[2][4][4];
        #pragma unroll
        for (int mt = 0; mt < 2; mt++)
            #pragma unroll
            for (int ntl = 0; ntl < 4; ntl++)
                #pragma unroll
                for (int q = 0; q < 4; q++) c[mt][ntl][q] = 0.f;

        #pragma unroll
        for (int kt = 0; kt < 8; kt++) {
            uint32_t a[2][4];
            #pragma unroll
            for (int mt = 0; mt < 2; mt++) {
                int r = rbase + mt*16 + tg;
                a[mt][0] = __float_as_uint(h1s[ r     *H1_STR + kt*8 + tr    ]);
                a[mt][1] = __float_as_uint(h1s[(r + 8)*H1_STR + kt*8 + tr    ]);
                a[mt][2] = __float_as_uint(h1s[ r     *H1_STR + kt*8 + tr + 4]);
                a[mt][3] = __float_as_uint(h1s[(r + 8)*H1_STR + kt*8 + tr + 4]);
            }
            #pragma unroll
            for (int ntl = 0; ntl < 4; ntl++) {
                int nt = half*4 + ntl;
                uint32_t bf0 = __float_as_uint(w2s[(kt*8 + tr    )*W2_STR + nt*8 + tg]);
                uint32_t bf1 = __float_as_uint(w2s[(kt*8 + tr + 4)*W2_STR + nt*8 + tg]);
                mma_tf32(c[0][ntl], a[0][0], a[0][1], a[0][2], a[0][3], bf0, bf1);
                mma_tf32(c[1][ntl], a[1][0], a[1][1], a[1][2], a[1][3], bf0, bf1);
            }
        }

        // layer-3 partials for this half (packed GELU on (row tg, row tg+8) pairs)
        #pragma unroll
        for (int ntl = 0; ntl < 4; ntl++) {
            int nt = half*4 + ntl;
            #pragma unroll
            for (int cc = 0; cc < 2; cc++) {
                int n = nt*8 + 2*tr + cc;
                float b2n = b2s[n];
                u64 b2n2 = pk2(b2n, b2n);
                u64 w3p0 = *reinterpret_cast<const u64*>(&w3s[n*8    ]);
                u64 w3p1 = *reinterpret_cast<const u64*>(&w3s[n*8 + 2]);
                u64 w3p2 = *reinterpret_cast<const u64*>(&w3s[n*8 + 4]);
                u64 w3p3 = *reinterpret_cast<const u64*>(&w3s[n*8 + 6]);
                #pragma unroll
                for (int mt = 0; mt < 2; mt++) {
                    u64 cin = pk2(c[mt][ntl][cc], c[mt][ntl][cc + 2]);
                    cin = add2(cin, b2n2);
                    u64 g2 = gelu_t2(cin, CA, CB, CH);
                    float glo, ghi; upk2(glo, ghi, g2);
                    u64 g2lo = pk2(glo, glo);
                    u64 g2hi = pk2(ghi, ghi);
                    u64* olo = outP[mt*2 + 0];
                    u64* ohi = outP[mt*2 + 1];
                    olo[0] = fma2(g2lo, w3p0, olo[0]); olo[1] = fma2(g2lo, w3p1, olo[1]);
                    olo[2] = fma2(g2lo, w3p2, olo[2]); olo[3] = fma2(g2lo, w3p3, olo[3]);
                    ohi[0] = fma2(g2hi, w3p0, ohi[0]); ohi[1] = fma2(g2hi, w3p1, ohi[1]);
                    ohi[2] = fma2(g2hi, w3p2, ohi[2]); ohi[3] = fma2(g2hi, w3p3, ohi[3]);
                }
            }
        }
    }

    // ---- reduce across 4 threads sharing each row; write bias (packed GELU)
    #pragma unroll
    for (int rr = 0; rr < 4; rr++) {
        int mt = rr >> 1, hi = rr & 1;
        int lpos = rbase + mt*16 + tg + hi*8;
        int pos = pos0 + lpos;
        float outA[8];
        #pragma unroll
        for (int j = 0; j < 4; j++) upk2(outA[2*j], outA[2*j+1], outP[rr][j]);
        #pragma unroll
        for (int h = 0; h < 8; h++) {
            float v = outA[h];
            v += __shfl_xor_sync(0xffffffffu, v, 1);
            v += __shfl_xor_sync(0xffffffffu, v, 2);
            outA[h] = v;
        }
        int b  = pos >> 16;
        int ij = pos & 65535;
        size_t base = ((size_t)b * 8) * 65536 + (size_t)ij;
        int h0 = 2*tr;
        u64 oin = pk2(outA[h0] + b3s[h0], outA[h0 + 1] + b3s[h0 + 1]);
        u64 og = gelu_t2(oin, CA, CB, CH);
        float g0o, g1o; upk2(g0o, g1o, og);
        g_bias[base + (size_t)(h0    )*65536] = g0o;
        g_bias[base + (size_t)(h0 + 1)*65536] = g1o;
    }
}

// ---------------- Kernel 2: LayerNorm (tf32-rounded output) ------------------
__global__ void ln_kernel(const float* __restrict__ x,
                          const float* __restrict__ gg, const float* __restrict__ bb,
                          float* __restrict__ y)
{
    int w = threadIdx.x >> 5, lane = threadIdx.x & 31;
    int row = blockIdx.x * 8 + w;
    const float4* xr = reinterpret_cast<const float4*>(x + (size_t)row * 256);
    float4 a = xr[lane*2], c = xr[lane*2 + 1];
    float s = a.x + a.y + a.z + a.w + c.x + c.y + c.z + c.w;
    #pragma unroll
    for (int o = 16; o; o >>= 1) s += __shfl_xor_sync(0xffffffffu, s, o);
    float mu = s * (1.0f / 256.0f);
    float dx[8] = {a.x-mu, a.y-mu, a.z-mu, a.w-mu, c.x-mu, c.y-mu, c.z-mu, c.w-mu};
    float ss = 0.f;
    #pragma unroll
    for (int q = 0; q < 8; q++) ss += dx[q]*dx[q];
    #pragma unroll
    for (int o = 16; o; o >>= 1) ss += __shfl_xor_sync(0xffffffffu, ss, o);
    float rstd = rsqrtf(ss * (1.0f/256.0f) + 1e-5f);
    const float4* gr = reinterpret_cast<const float4*>(gg);
    const float4* br = reinterpret_cast<const float4*>(bb);
    float4 g0 = gr[lane*2], g1 = gr[lane*2+1];
    float4 b0 = br[lane*2], b1 = br[lane*2+1];
    float4 o0, o1;
    o0.x = tf32r(fmaf(dx[0]*rstd, g0.x, b0.x)); o0.y = tf32r(fmaf(dx[1]*rstd, g0.y, b0.y));
    o0.z = tf32r(fmaf(dx[2]*rstd, g0.z, b0.z)); o0.w = tf32r(fmaf(dx[3]*rstd, g0.w, b0.w));
    o1.x = tf32r(fmaf(dx[4]*rstd, g1.x, b1.x)); o1.y = tf32r(fmaf(dx[5]*rstd, g1.y, b1.y));
    o1.z = tf32r(fmaf(dx[6]*rstd, g1.z, b1.z)); o1.w = tf32r(fmaf(dx[7]*rstd, g1.w, b1.w));
    float4* yr = reinterpret_cast<float4*>(y + (size_t)row * 256);
    yr[lane*2] = o0; yr[lane*2 + 1] = o1;
}

// ---------------- Kernel 3: tf32 TC GEMM, cp.async double-buffered -----------
#define SA 4608              // 128*36 floats
#define SB 2304              // 32*72 floats
#define STG (SA + SB)        // per-stage floats
#define GEMM_SMEM (2*STG*4)  // 55296 bytes
template<int ACT, bool RES, bool CVT>
__global__ void __launch_bounds__(256) gemm_tc(
    const float* __restrict__ A, const float* __restrict__ W,
    const float* __restrict__ bias, const float* __restrict__ res,
    float* __restrict__ C, int K, int Nc)
{
    extern __shared__ float smx[];
    int tid = threadIdx.x;
    int lane = tid & 31, warp = tid >> 5;
    int tg = lane >> 2, tr = lane & 3;
    int wm = warp & 3, wn = warp >> 2;
    int row0 = blockIdx.y * 128, col0 = blockIdx.x * 64;

    float c[2][4][4];
    #pragma unroll
    for (int mt = 0; mt < 2; mt++)
        #pragma unroll
        for (int nt = 0; nt < 4; nt++)
            #pragma unroll
            for (int q = 0; q < 4; q++) c[mt][nt][q] = 0.f;

    int ar = tid >> 1, ah = (tid & 1) * 16;
    int br = tid >> 3, bc = (tid & 7) * 8;
    const float* Ap = A + (size_t)(row0 + ar) * K + ah;
    const float* Wp = W + (size_t)br * Nc + col0 + bc;
    uint32_t sbase = (uint32_t)__cvta_generic_to_shared(smx);

    auto issue = [&](int k0, int stg) {
        uint32_t sa = sbase + (stg*STG + ar*36 + ah) * 4u;
        #pragma unroll
        for (int q = 0; q < 4; q++) cpa16(sa + q*16, Ap + k0 + q*4);
        uint32_t sb = sbase + (stg*STG + SA + br*72 + bc) * 4u;
        cpa16(sb,      Wp + (size_t)k0 * Nc);
        cpa16(sb + 16, Wp + (size_t)k0 * Nc + 4);
        cpa_commit();
    };

    issue(0, 0);
    int cur = 0;
    for (int k0 = 0; k0 < K; k0 += 32) {
        bool hasNext = (k0 + 32) < K;
        if (hasNext) { issue(k0 + 32, cur ^ 1); cpa_wait<1>(); }
        else         { cpa_wait<0>(); }
        __syncthreads();

        const float* As = smx + cur*STG;
        const float* Bs = As + SA;
        #pragma unroll
        for (int kk = 0; kk < 4; kk++) {
            uint32_t bf0[4], bf1[4];
            #pragma unroll
            for (int nt = 0; nt < 4; nt++) {
                bf0[nt] = __float_as_uint(Bs[(kk*8 + tr    )*72 + wn*32 + nt*8 + tg]);
                bf1[nt] = __float_as_uint(Bs[(kk*8 + tr + 4)*72 + wn*32 + nt*8 + tg]);
            }
            #pragma unroll
            for (int mt = 0; mt < 2; mt++) {
                int rr = wm*32 + mt*16 + tg;
                uint32_t fa0 = __float_as_uint(As[ rr     *36 + kk*8 + tr    ]);
                uint32_t fa1 = __float_as_uint(As[(rr + 8)*36 + kk*8 + tr    ]);
                uint32_t fa2 = __float_as_uint(As[ rr     *36 + kk*8 + tr + 4]);
                uint32_t fa3 = __float_as_uint(As[(rr + 8)*36 + kk*8 + tr + 4]);
                #pragma unroll
                for (int nt = 0; nt < 4; nt++)
                    mma_tf32(c[mt][nt], fa0, fa1, fa2, fa3, bf0[nt], bf1[nt]);
            }
        }
        __syncthreads();
        cur ^= 1;
    }

    #pragma unroll
    for (int mt = 0; mt < 2; mt++) {
        int r_lo = row0 + wm*32 + mt*16 + tg;
        #pragma unroll
        for (int nt = 0; nt < 4; nt++) {
            int cc0 = col0 + wn*32 + nt*8 + 2*tr;
            float bx = bias[cc0], by = bias[cc0 + 1];
            float v00 = c[mt][nt][0] + bx, v01 = c[mt][nt][1] + by;
            float v10 = c[mt][nt][2] + bx, v11 = c[mt][nt][3] + by;
            if (ACT == 1) { v00 = gelu_f(v00); v01 = gelu_f(v01); v10 = gelu_f(v10); v11 = gelu_f(v11); }
            if (RES) {
                v00 += res[(size_t)r_lo * Nc + cc0];     v01 += res[(size_t)r_lo * Nc + cc0 + 1];
                v10 += res[(size_t)(r_lo+8) * Nc + cc0]; v11 += res[(size_t)(r_lo+8) * Nc + cc0 + 1];
            }
            if (CVT) { v00 = tf32r(v00); v01 = tf32r(v01); v10 = tf32r(v10); v11 = tf32r(v11); }
            *reinterpret_cast<float2*>(&C[(size_t)r_lo * Nc + cc0])     = make_float2(v00, v01);
            *reinterpret_cast<float2*>(&C[(size_t)(r_lo+8) * Nc + cc0]) = make_float2(v10, v11);
        }
    }
}

// ---------------- Kernel 4: fused attention (transposed V tile) --------------
#define VT_STR 260
__global__ void attn_kernel(const unsigned char* __restrict__ mask)
{
    extern __shared__ float sm[];
    float* kT = sm;                   // [32][256]
    float* vT = sm + 32*256;          // [32][260]
    float* pS = vT + 32*VT_STR;       // [16][256]

    int bh = blockIdx.x;
    int b = bh >> 3, h = bh & 7;
    int tid = threadIdx.x;
    int w = tid >> 5, lane = tid & 31;

    const float* kp = g_qkv + ((size_t)(b*256 + tid)) * 768 + 256 + h*32;
    const float* vp = kp + 256;
    #pragma unroll
    for (int q = 0; q < 8; q++) {
        float4 kv = *reinterpret_cast<const float4*>(kp + q*4);
        kT[(q*4+0)*256 + tid] = kv.x;
        kT[(q*4+1)*256 + tid] = kv.y;
        kT[(q*4+2)*256 + tid] = kv.z;
        kT[(q*4+3)*256 + tid] = kv.w;
        float4 vv = *reinterpret_cast<const float4*>(vp + q*4);
        vT[(q*4+0)*VT_STR + tid] = vv.x;
        vT[(q*4+1)*VT_STR + tid] = vv.y;
        vT[(q*4+2)*VT_STR + tid] = vv.z;
        vT[(q*4+3)*VT_STR + tid] = vv.w;
    }
    __syncthreads();

    const float isq = 0.17677669529663689f;
    const unsigned char* mp = mask + b*256;
    uchar4 m0 = *reinterpret_cast<const uchar4*>(mp + lane*4);
    uchar4 m1 = *reinterpret_cast<const uchar4*>(mp + 128 + lane*4);

    int t0 = blockIdx.y * 64;
    for (int t = 0; t < 4; t++) {
        int r0 = t0 + t*16 + w*2;
        const float* qp0 = g_qkv + ((size_t)(b*256 + r0)) * 768 + h*32;
        const float* qp1 = qp0 + 768;
        float qr0[32], qr1[32];
        #pragma unroll
        for (int q = 0; q < 8; q++) {
            float4 f0 = *reinterpret_cast<const float4*>(qp0 + q*4);
            qr0[q*4+0] = f0.x; qr0[q*4+1] = f0.y; qr0[q*4+2] = f0.z; qr0[q*4+3] = f0.w;
            float4 f1 = *reinterpret_cast<const float4*>(qp1 + q*4);
            qr1[q*4+0] = f1.x; qr1[q*4+1] = f1.y; qr1[q*4+2] = f1.z; qr1[q*4+3] = f1.w;
        }
        u64 A0[4] = {0,0,0,0}, A1[4] = {0,0,0,0};
        #pragma unroll
        for (int hd = 0; hd < 32; hd++) {
            float4 k0 = *reinterpret_cast<const float4*>(&kT[hd*256 + lane*4]);
            float4 k1 = *reinterpret_cast<const float4*>(&kT[hd*256 + 128 + lane*4]);
            const u64* k0p = reinterpret_cast<const u64*>(&k0);
            const u64* k1p = reinterpret_cast<const u64*>(&k1);
            u64 q0p = pk2(qr0[hd], qr0[hd]);
            u64 q1p = pk2(qr1[hd], qr1[hd]);
            A0[0] = fma2(q0p, k0p[0], A0[0]); A0[1] = fma2(q0p, k0p[1], A0[1]);
            A0[2] = fma2(q0p, k1p[0], A0[2]); A0[3] = fma2(q0p, k1p[1], A0[3]);
            A1[0] = fma2(q1p, k0p[0], A1[0]); A1[1] = fma2(q1p, k0p[1], A1[1]);
            A1[2] = fma2(q1p, k1p[0], A1[2]); A1[3] = fma2(q1p, k1p[1], A1[3]);
        }
        float a0[8], a1[8];
        #pragma unroll
        for (int j = 0; j < 4; j++) {
            upk2(a0[2*j], a0[2*j+1], A0[j]);
            upk2(a1[2*j], a1[2*j+1], A1[j]);
        }

        #pragma unroll
        for (int rr = 0; rr < 2; rr++) {
            float* acc = rr ? a1 : a0;
            int i = r0 + rr;
            const float* bp = g_bias + ((size_t)bh * 256 + i) * 256;
            float4 bb0 = *reinterpret_cast<const float4*>(bp + lane*4);
            float4 bb1 = *reinterpret_cast<const float4*>(bp + 128 + lane*4);
            float l[8];
            l[0] = fmaf(acc[0], isq, bb0.x); l[1] = fmaf(acc[1], isq, bb0.y);
            l[2] = fmaf(acc[2], isq, bb0.z); l[3] = fmaf(acc[3], isq, bb0.w);
            l[4] = fmaf(acc[4], isq, bb1.x); l[5] = fmaf(acc[5], isq, bb1.y);
            l[6] = fmaf(acc[6], isq, bb1.z); l[7] = fmaf(acc[7], isq, bb1.w);
            if (m0.x) l[0] = -CUDART_INF_F; if (m0.y) l[1] = -CUDART_INF_F;
            if (m0.z) l[2] = -CUDART_INF_F; if (m0.w) l[3] = -CUDART_INF_F;
            if (m1.x) l[4] = -CUDART_INF_F; if (m1.y) l[5] = -CUDART_INF_F;
            if (m1.z) l[6] = -CUDART_INF_F; if (m1.w) l[7] = -CUDART_INF_F;

            float mx = l[0];
            #pragma unroll
            for (int c = 1; c < 8; c++) mx = fmaxf(mx, l[c]);
            #pragma unroll
            for (int o = 16; o; o >>= 1) mx = fmaxf(mx, __shfl_xor_sync(0xffffffffu, mx, o));
            float e[8], s = 0.f;
            #pragma unroll
            for (int c = 0; c < 8; c++) { e[c] = expf(l[c] - mx); s += e[c]; }
            #pragma unroll
            for (int o = 16; o; o >>= 1) s += __shfl_xor_sync(0xffffffffu, s, o);
            float inv = 1.0f / s;
            int pr = w*2 + rr;
            *reinterpret_cast<float4*>(&pS[pr*256 + lane*4]) =
                make_float4(e[0]*inv, e[1]*inv, e[2]*inv, e[3]*inv);
            *reinterpret_cast<float4*>(&pS[pr*256 + 128 + lane*4]) =
                make_float4(e[4]*inv, e[5]*inv, e[6]*inv, e[7]*inv);
        }
        __syncwarp();

        // PV: lane = hd; vT row contiguous -> one LDS.128 per 4 j's
        u64 O0 = 0ull, O1 = 0ull;
        const float* vrow = &vT[lane*VT_STR];
        #pragma unroll 8
        for (int j4 = 0; j4 < 64; j4++) {
            float4 p0 = *reinterpret_cast<const float4*>(&pS[(w*2    )*256 + j4*4]);
            float4 p1 = *reinterpret_cast<const float4*>(&pS[(w*2 + 1)*256 + j4*4]);
            float4 vv = *reinterpret_cast<const float4*>(vrow + j4*4);
            const u64* p0p = reinterpret_cast<const u64*>(&p0);
            const u64* p1p = reinterpret_cast<const u64*>(&p1);
            const u64* vvp = reinterpret_cast<const u64*>(&vv);
            O0 = fma2(p0p[0], vvp[0], O0); O0 = fma2(p0p[1], vvp[1], O0);
            O1 = fma2(p1p[0], vvp[0], O1); O1 = fma2(p1p[1], vvp[1], O1);
        }
        float o0lo, o0hi, o1lo, o1hi;
        upk2(o0lo, o0hi, O0); upk2(o1lo, o1hi, O1);
        g_attout[((size_t)(b*256 + r0    )) * 256 + h*32 + lane] = tf32r(o0lo + o0hi);
        g_attout[((size_t)(b*256 + r0 + 1)) * 256 + h*32 + lane] = tf32r(o1lo + o1hi);
        __syncwarp();
    }
}

// ---------------- launch (serial — fork reverted) ----------------------------
extern "C" void kernel_launch(void* const* d_in, const int* in_sizes, int n_in,
                              void* d_out, int out_size)
{
    const float* x      = (const float*)d_in[0];
    const float* u      = (const float*)d_in[1];
    const unsigned char* mask = (const unsigned char*)d_in[2];
    const float* n1_g   = (const float*)d_in[3];
    const float* n1_b   = (const float*)d_in[4];
    const float* qkv_w  = (const float*)d_in[5];
    const float* qkv_b  = (const float*)d_in[6];
    const float* proj_w = (const float*)d_in[7];
    const float* proj_b = (const float*)d_in[8];
    const float* n2_g   = (const float*)d_in[9];
    const float* n2_b   = (const float*)d_in[10];
    const float* mlp_w1 = (const float*)d_in[11];
    const float* mlp_b1 = (const float*)d_in[12];
    const float* mlp_w2 = (const float*)d_in[13];
    const float* mlp_b2 = (const float*)d_in[14];
    const float* pw_w1  = (const float*)d_in[15];
    const float* pw_b1  = (const float*)d_in[16];
    const float* pw_w2  = (const float*)d_in[17];
    const float* pw_b2  = (const float*)d_in[18];
    const float* pw_w3  = (const float*)d_in[19];
    const float* pw_b3  = (const float*)d_in[20];
    float* out = (float*)d_out;

    float* xn  = nullptr; float* qkv = nullptr; float* ao = nullptr;
    float* x2  = nullptr; float* hid = nullptr; float* wt = nullptr;
    cudaGetSymbolAddress((void**)&xn,  g_xn);
    cudaGetSymbolAddress((void**)&qkv, g_qkv);
    cudaGetSymbolAddress((void**)&ao,  g_attout);
    cudaGetSymbolAddress((void**)&x2,  g_x2);
    cudaGetSymbolAddress((void**)&hid, g_hid);
    cudaGetSymbolAddress((void**)&wt,  g_wt);

    cudaFuncSetAttribute(gemm_tc<0,false,false>, cudaFuncAttributeMaxDynamicSharedMemorySize, GEMM_SMEM);
    cudaFuncSetAttribute(gemm_tc<0,true,false>,  cudaFuncAttributeMaxDynamicSharedMemorySize, GEMM_SMEM);
    cudaFuncSetAttribute(gemm_tc<1,false,true>,  cudaFuncAttributeMaxDynamicSharedMemorySize, GEMM_SMEM);
    cudaFuncSetAttribute(gemm_tc<1,true,false>,  cudaFuncAttributeMaxDynamicSharedMemorySize, GEMM_SMEM);

    // 0) weight tf32 conversion
    cvtw_kernel<<<786432/256, 256>>>(qkv_w, proj_w, mlp_w1, mlp_w2);

    // 1) pairwise bias MLP
    {
        int smem = (64*W2_STR + 256*H1_STR) * (int)sizeof(float);
        cudaFuncSetAttribute(pairwise_kernel, cudaFuncAttributeMaxDynamicSharedMemorySize, smem);
        pairwise_kernel<<<Bq*Nq*Nq/256, 256, smem>>>(u, pw_w1, pw_b1, pw_w2, pw_b2, pw_w3, pw_b3);
    }

    // 2) LN1 + qkv GEMM
    ln_kernel<<<ROWS/8, 256>>>(x, n1_g, n1_b, xn);
    gemm_tc<0,false,false><<<dim3(3*Dq/64, ROWS/128), 256, GEMM_SMEM>>>(
        xn, wt, qkv_b, nullptr, qkv, Dq, 3*Dq);

    // 3) attention
    {
        int smem = (32*256 + 32*VT_STR + 16*256) * (int)sizeof(float);
        cudaFuncSetAttribute(attn_kernel, cudaFuncAttributeMaxDynamicSharedMemorySize, smem);
        dim3 grid(Bq*Hq, 4);
        attn_kernel<<<grid, 256, smem>>>(mask);
    }

    // 4) proj + residual
    gemm_tc<0,true,false><<<dim3(Dq/64, ROWS/128), 256, GEMM_SMEM>>>(
        ao, wt + 196608, proj_b, x, x2, Dq, Dq);

    // 5) LN2 + MLP
    ln_kernel<<<ROWS/8, 256>>>(x2, n2_g, n2_b, xn);
    gemm_tc<1,false,true><<<dim3(DFF/64, ROWS/128), 256, GEMM_SMEM>>>(
        xn, wt + 262144, mlp_b1, nullptr, hid, Dq, DFF);
    gemm_tc<1,true,false><<<dim3(Dq/64, ROWS/128), 256, GEMM_SMEM>>>(
        hid, wt + 524288, mlp_b2, x2, out, DFF, Dq);
}